// round 1
// baseline (speedup 1.0000x reference)
#include <cuda_runtime.h>

// InterAttention (ESIM-style) on GB300.
// Pipeline:
//   r1m = lrelu(lrelu(r1@W1+b1)@W2+b2)*m1    (same for r2 with m2)
//   S   = r1m @ r2m^T + (-1e10 where !(m1&m2))
//   o1  = softmax_rows(S)*mpos ; o2 = softmax_cols(S)*mpos
//   r1c = o1 @ r2m ; r2c = o2^T @ r1m
//   out1 = lrelu(lrelu([r1m|r1c]@Wc1+bc1)@Wc2+bc2)*m1   (same for out2)

#define NEG_INF_F (-1e10f)
#define SLOPE 0.01f

#define Bc 64
#define Lc 512
#define Dc 512
#define BLD (Bc*Lc*Dc)   // 16,777,216 elements

// Scratch (static device memory; allocation APIs are forbidden)
__device__ float g_h[BLD];     // hidden / reused
__device__ float g_r1m[BLD];
__device__ float g_r2m[BLD];
__device__ float g_S[BLD];
__device__ float g_o1[BLD];
__device__ float g_o2[BLD];
__device__ float g_c1[BLD];
__device__ float g_c2[BLD];

// ---------------- Tiled SGEMM ----------------
// C[b] = epilogue( op(A)[b] @ op(B)[b] )
// BM=BN=128, BK=8, 256 threads, 8x8 micro-tile per thread.
// mode: 0 = plain
//       1 = bias + lrelu (+ optional per-row 0/1 mask)
//       2 = additive score mask from m1[b,row], m2[b,col]
// Concat along K: element (m,k) comes from A if k < Ksplit else A2 (k-Ksplit).
#define BM 128
#define BN 128
#define BK 8
#define TM 8
#define TN 8

__global__ __launch_bounds__(256)
void gemm_kernel(const float* __restrict__ A, const float* __restrict__ A2,
                 const float* __restrict__ B, float* __restrict__ C,
                 int M, int N, int K, int Ksplit,
                 int ldA, int ldA2, int ldB, int ldC,
                 long sA, long sA2, long sB, long sC,
                 int transA, int transB,
                 const float* __restrict__ bias,
                 const int* __restrict__ rowmask,
                 const int* __restrict__ m1p, const int* __restrict__ m2p,
                 int mode)
{
    const int b = blockIdx.z;
    const float* Ab  = A  + (long)b * sA;
    const float* A2b = A2 + (long)b * sA2;
    const float* Bb  = B  + (long)b * sB;
    float*       Cb  = C  + (long)b * sC;

    __shared__ float As[BK][BM];
    __shared__ float Bs[BK][BN];

    const int tid = threadIdx.x;
    const int mBlock = blockIdx.y * BM;
    const int nBlock = blockIdx.x * BN;

    const int mThread = (tid >> 4) * TM;   // 0..120
    const int nThread = (tid & 15) * TN;   // 0..120

    float acc[TM][TN];
#pragma unroll
    for (int i = 0; i < TM; i++)
#pragma unroll
        for (int j = 0; j < TN; j++) acc[i][j] = 0.0f;

    for (int k0 = 0; k0 < K; k0 += BK) {
        // ---- load A tile into As[k][m] ----
        if (!transA) {
            const float* Ap; int kb, ld;
            if (k0 < Ksplit) { Ap = Ab;  kb = k0;          ld = ldA;  }
            else             { Ap = A2b; kb = k0 - Ksplit; ld = ldA2; }
            int r  = tid >> 1;          // 0..127 (m)
            int kc = (tid & 1) * 4;     // 0 or 4 (k)
            float4 v = *(const float4*)(Ap + (long)(mBlock + r) * ld + kb + kc);
            As[kc + 0][r] = v.x; As[kc + 1][r] = v.y;
            As[kc + 2][r] = v.z; As[kc + 3][r] = v.w;
        } else {
            // op(A)[m,k] = A[k*ldA + m]
            int r = tid >> 5;           // 0..7 (k)
            int c = (tid & 31) * 4;     // 0..124 (m)
            float4 v = *(const float4*)(Ab + (long)(k0 + r) * ldA + mBlock + c);
            *(float4*)&As[r][c] = v;
        }
        // ---- load B tile into Bs[k][n] ----
        if (!transB) {
            int r = tid >> 5;           // k
            int c = (tid & 31) * 4;     // n
            float4 v = *(const float4*)(Bb + (long)(k0 + r) * ldB + nBlock + c);
            *(float4*)&Bs[r][c] = v;
        } else {
            // op(B)[k,n] = B[n*ldB + k]
            int r  = tid >> 1;          // n
            int kc = (tid & 1) * 4;     // k
            float4 v = *(const float4*)(Bb + (long)(nBlock + r) * ldB + k0 + kc);
            Bs[kc + 0][r] = v.x; Bs[kc + 1][r] = v.y;
            Bs[kc + 2][r] = v.z; Bs[kc + 3][r] = v.w;
        }
        __syncthreads();

#pragma unroll
        for (int k = 0; k < BK; k++) {
            float a[TM], bb[TN];
#pragma unroll
            for (int i = 0; i < TM; i++) a[i]  = As[k][mThread + i];
#pragma unroll
            for (int j = 0; j < TN; j++) bb[j] = Bs[k][nThread + j];
#pragma unroll
            for (int i = 0; i < TM; i++)
#pragma unroll
                for (int j = 0; j < TN; j++)
                    acc[i][j] += a[i] * bb[j];
        }
        __syncthreads();
    }

    // ---- epilogue ----
#pragma unroll
    for (int i = 0; i < TM; i++) {
        int row = mBlock + mThread + i;
        float rm = 1.0f;
        int mi = 1;
        if (mode == 1 && rowmask) rm = rowmask[(long)b * M + row] ? 1.0f : 0.0f;
        if (mode == 2) mi = m1p[(long)b * M + row];
#pragma unroll
        for (int j = 0; j < TN; j++) {
            int col = nBlock + nThread + j;
            float v = acc[i][j];
            if (mode == 1) {
                v += bias[col];
                v = (v >= 0.0f) ? v : SLOPE * v;
                v *= rm;
            } else if (mode == 2) {
                int mj = m2p[(long)b * N + col];
                v += (mi && mj) ? 0.0f : NEG_INF_F;
            }
            Cb[(long)row * ldC + col] = v;
        }
    }
}

// ---------------- Row softmax: o1[b,i,:] = softmax(S[b,i,:]) * mpos ----------------
__global__ __launch_bounds__(256)
void softmax_row_kernel(const float* __restrict__ S, float* __restrict__ O,
                        const int* __restrict__ m1, const int* __restrict__ m2)
{
    const int b = blockIdx.y, i = blockIdx.x;
    const float* row = S + ((long)b * Lc + i) * Lc;
    float* orow      = O + ((long)b * Lc + i) * Lc;
    const int tid = threadIdx.x;   // 256 threads, 2 elems each

    float v0 = row[tid], v1 = row[tid + 256];
    __shared__ float red[256];

    red[tid] = fmaxf(v0, v1);
    __syncthreads();
    for (int s = 128; s > 0; s >>= 1) {
        if (tid < s) red[tid] = fmaxf(red[tid], red[tid + s]);
        __syncthreads();
    }
    float mx = red[0];
    __syncthreads();

    float e0 = __expf(v0 - mx), e1 = __expf(v1 - mx);
    red[tid] = e0 + e1;
    __syncthreads();
    for (int s = 128; s > 0; s >>= 1) {
        if (tid < s) red[tid] += red[tid + s];
        __syncthreads();
    }
    float inv = 1.0f / red[0];

    int mi = m1[b * Lc + i];
    float f0 = (mi && m2[b * Lc + tid])       ? 1.0f : 0.0f;
    float f1 = (mi && m2[b * Lc + tid + 256]) ? 1.0f : 0.0f;
    orow[tid]       = e0 * inv * f0;
    orow[tid + 256] = e1 * inv * f1;
}

// ---------------- Column softmax: o2[b,:,j] = softmax over i of S[b,:,j] * mpos ----------------
__global__ __launch_bounds__(1024)
void softmax_col_kernel(const float* __restrict__ S, float* __restrict__ O,
                        const int* __restrict__ m1, const int* __restrict__ m2)
{
    const int b  = blockIdx.y;
    const int tx = threadIdx.x, ty = threadIdx.y;   // 32x32
    const int j  = blockIdx.x * 32 + tx;
    const float* Sb = S + (long)b * Lc * Lc;
    float* Ob       = O + (long)b * Lc * Lc;

    float vals[16];
    float lmax = -1e30f;
#pragma unroll
    for (int it = 0; it < 16; it++) {
        int i = ty + it * 32;
        vals[it] = Sb[(long)i * Lc + j];
        lmax = fmaxf(lmax, vals[it]);
    }
    __shared__ float red[32][33];
    red[ty][tx] = lmax;
    __syncthreads();
    for (int s = 16; s > 0; s >>= 1) {
        if (ty < s) red[ty][tx] = fmaxf(red[ty][tx], red[ty + s][tx]);
        __syncthreads();
    }
    float mx = red[0][tx];
    __syncthreads();

    float lsum = 0.0f;
#pragma unroll
    for (int it = 0; it < 16; it++) {
        vals[it] = __expf(vals[it] - mx);
        lsum += vals[it];
    }
    red[ty][tx] = lsum;
    __syncthreads();
    for (int s = 16; s > 0; s >>= 1) {
        if (ty < s) red[ty][tx] += red[ty + s][tx];
        __syncthreads();
    }
    float inv = 1.0f / red[0][tx];

    int mj = m2[b * Lc + j];
#pragma unroll
    for (int it = 0; it < 16; it++) {
        int i = ty + it * 32;
        float f = (mj && m1[b * Lc + i]) ? 1.0f : 0.0f;
        Ob[(long)i * Lc + j] = vals[it] * inv * f;
    }
}

// ---------------- Launch ----------------
extern "C" void kernel_launch(void* const* d_in, const int* in_sizes, int n_in,
                              void* d_out, int out_size)
{
    const float* r1    = (const float*)d_in[0];
    const float* r2    = (const float*)d_in[1];
    const int*   mask1 = (const int*)  d_in[2];
    const int*   mask2 = (const int*)  d_in[3];
    const float* W1    = (const float*)d_in[4];
    const float* b1    = (const float*)d_in[5];
    const float* W2    = (const float*)d_in[6];
    const float* b2    = (const float*)d_in[7];
    const float* Wc1   = (const float*)d_in[8];   // [1024, 512]
    const float* bc1   = (const float*)d_in[9];
    const float* Wc2   = (const float*)d_in[10];
    const float* bc2   = (const float*)d_in[11];
    float* out = (float*)d_out;

    float *h, *r1m, *r2m, *S, *o1, *o2, *c1, *c2;
    cudaGetSymbolAddress((void**)&h,   g_h);
    cudaGetSymbolAddress((void**)&r1m, g_r1m);
    cudaGetSymbolAddress((void**)&r2m, g_r2m);
    cudaGetSymbolAddress((void**)&S,   g_S);
    cudaGetSymbolAddress((void**)&o1,  g_o1);
    cudaGetSymbolAddress((void**)&o2,  g_o2);
    cudaGetSymbolAddress((void**)&c1,  g_c1);
    cudaGetSymbolAddress((void**)&c2,  g_c2);

    const long LL = (long)Lc * Lc;   // 262144, batch stride for [L,L] and [L,D]
    dim3 blk(256);
    dim3 gridMlp(Dc / BN, (Bc * Lc) / BM, 1);   // (4, 256, 1)
    dim3 gridBat(Lc / BN, Lc / BM, Bc);         // (4, 4, 64)

    // ---- MLP on r1 ----
    gemm_kernel<<<gridMlp, blk>>>(r1, r1, W1, h,
        Bc * Lc, Dc, Dc, Dc, Dc, Dc, Dc, Dc, 0, 0, 0, 0, 0, 0,
        b1, nullptr, nullptr, nullptr, 1);
    gemm_kernel<<<gridMlp, blk>>>(h, h, W2, r1m,
        Bc * Lc, Dc, Dc, Dc, Dc, Dc, Dc, Dc, 0, 0, 0, 0, 0, 0,
        b2, mask1, nullptr, nullptr, 1);
    // ---- MLP on r2 ----
    gemm_kernel<<<gridMlp, blk>>>(r2, r2, W1, h,
        Bc * Lc, Dc, Dc, Dc, Dc, Dc, Dc, Dc, 0, 0, 0, 0, 0, 0,
        b1, nullptr, nullptr, nullptr, 1);
    gemm_kernel<<<gridMlp, blk>>>(h, h, W2, r2m,
        Bc * Lc, Dc, Dc, Dc, Dc, Dc, Dc, Dc, 0, 0, 0, 0, 0, 0,
        b2, mask2, nullptr, nullptr, 1);

    // ---- Scores: S = r1m @ r2m^T + mask_inf ----
    gemm_kernel<<<gridBat, blk>>>(r1m, r1m, r2m, S,
        Lc, Lc, Dc, Dc, Dc, Dc, Dc, Lc, LL, LL, LL, LL, 0, 1,
        nullptr, nullptr, mask1, mask2, 2);

    // ---- Softmaxes ----
    softmax_row_kernel<<<dim3(Lc, Bc), 256>>>(S, o1, mask1, mask2);
    softmax_col_kernel<<<dim3(Lc / 32, Bc), dim3(32, 32)>>>(S, o2, mask1, mask2);

    // ---- r1_c = o1 @ r2m ----
    gemm_kernel<<<gridBat, blk>>>(o1, o1, r2m, c1,
        Lc, Dc, Lc, Lc, Lc, Lc, Dc, Dc, LL, LL, LL, LL, 0, 0,
        nullptr, nullptr, nullptr, nullptr, 0);
    // ---- r2_c = o2^T @ r1m ----
    gemm_kernel<<<gridBat, blk>>>(o2, o2, r1m, c2,
        Lc, Dc, Lc, Lc, Lc, Lc, Dc, Dc, LL, LL, LL, LL, 1, 0,
        nullptr, nullptr, nullptr, nullptr, 0);

    // ---- Compare for r1: [r1m | r1c] @ Wc1 (K=1024), then @ Wc2 ----
    gemm_kernel<<<gridMlp, blk>>>(r1m, c1, Wc1, h,
        Bc * Lc, Dc, 2 * Dc, Dc, Dc, Dc, Dc, Dc, 0, 0, 0, 0, 0, 0,
        bc1, nullptr, nullptr, nullptr, 1);
    gemm_kernel<<<gridMlp, blk>>>(h, h, Wc2, out,
        Bc * Lc, Dc, Dc, Dc, Dc, Dc, Dc, Dc, 0, 0, 0, 0, 0, 0,
        bc2, mask1, nullptr, nullptr, 1);

    // ---- Compare for r2 ----
    gemm_kernel<<<gridMlp, blk>>>(r2m, c2, Wc1, h,
        Bc * Lc, Dc, 2 * Dc, Dc, Dc, Dc, Dc, Dc, 0, 0, 0, 0, 0, 0,
        bc1, nullptr, nullptr, nullptr, 1);
    gemm_kernel<<<gridMlp, blk>>>(h, h, Wc2, out + (long)BLD,
        Bc * Lc, Dc, Dc, Dc, Dc, Dc, Dc, Dc, 0, 0, 0, 0, 0, 0,
        bc2, mask2, nullptr, nullptr, 1);
}

// round 5
// speedup vs baseline: 2.9086x; 2.9086x over previous
#include <cuda_runtime.h>
#include <cstdint>

// InterAttention (ESIM-style) on GB300 — tf32 tensor-core version.
//   r1m = lrelu(lrelu(r1@W1+b1)@W2+b2)*m1
//   S   = r1m @ r2m^T + (-1e10 where !(m1&m2))
//   o1  = softmax_rows(S)*mpos ; o2 = softmax_cols(S)*mpos
//   r1c = o1 @ r2m ; r2c = o2^T @ r1m
//   out = lrelu(lrelu([xm|xc]@Wc1+bc1)@Wc2+bc2)*mask
//
// All GEMMs run through one tf32 mma.sync kernel with K-contiguous operands:
// weights are pre-transposed, r1m/r2m transposed once, col-softmax writes o2^T.

#define NEG_INF_F (-1e10f)
#define SLOPE 0.01f

#define Bc 64
#define Lc 512
#define Dc 512
#define BLD (Bc*Lc*Dc)   // 16,777,216

// ---- scratch (static device memory) ----
__device__ float g_h[BLD];
__device__ float g_r1m[BLD];
__device__ float g_r2m[BLD];
__device__ float g_r1mT[BLD];
__device__ float g_r2mT[BLD];
__device__ float g_S[BLD];
__device__ float g_o1[BLD];
__device__ float g_o2T[BLD];
__device__ float g_c1[BLD];
__device__ float g_c2[BLD];
__device__ float g_W1T[Dc*Dc];
__device__ float g_W2T[Dc*Dc];
__device__ float g_Wc1T[2*Dc*Dc];
__device__ float g_Wc2T[Dc*Dc];

__device__ __forceinline__ float to_tf32(float x) {
    float r;
    asm("cvt.rna.tf32.f32 %0, %1;" : "=f"(r) : "f"(x));
    return r;
}

__device__ __forceinline__ void mma_tf32(float* c, const uint32_t* a, const uint32_t* b) {
    asm volatile(
        "mma.sync.aligned.m16n8k8.row.col.f32.tf32.tf32.f32 "
        "{%0,%1,%2,%3}, {%4,%5,%6,%7}, {%8,%9}, {%0,%1,%2,%3};"
        : "+f"(c[0]), "+f"(c[1]), "+f"(c[2]), "+f"(c[3])
        : "r"(a[0]), "r"(a[1]), "r"(a[2]), "r"(a[3]), "r"(b[0]), "r"(b[1]));
}

// ---------------- tf32 GEMM ----------------
// C[b][m][n] = epilogue( sum_k opA[b][m][k] * opB[b][n][k] )
// A: [M][K] row-major (K contiguous), optional concat with A2 at Ksplit.
// B: [N][K] row-major (K contiguous).
// mode 0: plain; 1: +bias, lrelu, *rowmask; 2: additive -inf mask from m1/m2.
#define BM 128
#define BN 128
#define BKK 16
#define SPAD 4
#define SW (BKK + SPAD)   // 20 floats -> 80B row stride (16B aligned)

__global__ __launch_bounds__(256, 2)
void gemm_tf32(const float* __restrict__ A, const float* __restrict__ A2,
               const float* __restrict__ B, float* __restrict__ C,
               int M, int N, int K, int Ksplit,
               int ldA, int ldA2, int ldB, int ldC,
               long sA, long sA2, long sB, long sC,
               const float* __restrict__ bias,
               const int* __restrict__ rowmask,
               const int* __restrict__ m1p, const int* __restrict__ m2p,
               int mode)
{
    __shared__ float As[2][BM][SW];
    __shared__ float Bs[2][BN][SW];

    const int b = blockIdx.z;
    const float* Ab  = A  + (long)b * sA;
    const float* A2b = A2 + (long)b * sA2;
    const float* Bb  = B  + (long)b * sB;
    float*       Cb  = C  + (long)b * sC;

    const int tid = threadIdx.x;
    const int mBlock = blockIdx.y * BM;
    const int nBlock = blockIdx.x * BN;

    // tile-load mapping: 128 rows x 16 floats, thread loads 8 floats (2 f4)
    const int lrow = tid >> 1;
    const int lc   = (tid & 1) * 8;

    // warp mapping: 8 warps, 2(m) x 4(n); warp tile 64x32
    const int warp = tid >> 5, lane = tid & 31;
    const int mw = (warp >> 2) * 64;
    const int nw = (warp & 3) * 32;
    const int gr = lane >> 2;     // group row
    const int tg = lane & 3;      // thread in group

    float acc[4][4][4];
#pragma unroll
    for (int i = 0; i < 4; i++)
#pragma unroll
        for (int j = 0; j < 4; j++)
#pragma unroll
            for (int q = 0; q < 4; q++) acc[i][j][q] = 0.0f;

    const int KT = K / BKK;
    float4 ra0, ra1, rb0, rb1;

    // ---- LDG for a given k0 ----
    auto do_ldg = [&](int k0) {
        const float* Ap; int kb, ld;
        if (k0 < Ksplit) { Ap = Ab;  kb = k0;          ld = ldA;  }
        else             { Ap = A2b; kb = k0 - Ksplit; ld = ldA2; }
        const float* pa = Ap + (long)(mBlock + lrow) * ld + kb + lc;
        ra0 = *(const float4*)(pa);
        ra1 = *(const float4*)(pa + 4);
        const float* pb = Bb + (long)(nBlock + lrow) * ldB + k0 + lc;
        rb0 = *(const float4*)(pb);
        rb1 = *(const float4*)(pb + 4);
    };
    // ---- convert + STS into buffer ----
    auto do_sts = [&](int buf) {
        float4 c0, c1;
        c0.x = to_tf32(ra0.x); c0.y = to_tf32(ra0.y); c0.z = to_tf32(ra0.z); c0.w = to_tf32(ra0.w);
        c1.x = to_tf32(ra1.x); c1.y = to_tf32(ra1.y); c1.z = to_tf32(ra1.z); c1.w = to_tf32(ra1.w);
        *(float4*)&As[buf][lrow][lc]     = c0;
        *(float4*)&As[buf][lrow][lc + 4] = c1;
        c0.x = to_tf32(rb0.x); c0.y = to_tf32(rb0.y); c0.z = to_tf32(rb0.z); c0.w = to_tf32(rb0.w);
        c1.x = to_tf32(rb1.x); c1.y = to_tf32(rb1.y); c1.z = to_tf32(rb1.z); c1.w = to_tf32(rb1.w);
        *(float4*)&Bs[buf][lrow][lc]     = c0;
        *(float4*)&Bs[buf][lrow][lc + 4] = c1;
    };

    do_ldg(0);
    do_sts(0);
    __syncthreads();

    for (int kt = 0; kt < KT; kt++) {
        const int buf = kt & 1;
        if (kt + 1 < KT) do_ldg((kt + 1) * BKK);

        // compute on As[buf], Bs[buf]
#pragma unroll
        for (int ks = 0; ks < 2; ks++) {
            const int kb = ks * 8;
            uint32_t af[4][4], bf[4][2];
#pragma unroll
            for (int mt = 0; mt < 4; mt++) {
                const int mr = mw + mt * 16;
                af[mt][0] = __float_as_uint(As[buf][mr + gr][kb + tg]);
                af[mt][1] = __float_as_uint(As[buf][mr + gr + 8][kb + tg]);
                af[mt][2] = __float_as_uint(As[buf][mr + gr][kb + tg + 4]);
                af[mt][3] = __float_as_uint(As[buf][mr + gr + 8][kb + tg + 4]);
            }
#pragma unroll
            for (int nt = 0; nt < 4; nt++) {
                const int nr = nw + nt * 8 + gr;
                bf[nt][0] = __float_as_uint(Bs[buf][nr][kb + tg]);
                bf[nt][1] = __float_as_uint(Bs[buf][nr][kb + tg + 4]);
            }
#pragma unroll
            for (int mt = 0; mt < 4; mt++)
#pragma unroll
                for (int nt = 0; nt < 4; nt++)
                    mma_tf32(acc[mt][nt], af[mt], bf[nt]);
        }

        if (kt + 1 < KT) do_sts((kt + 1) & 1);
        __syncthreads();
    }

    // ---- epilogue ----
#pragma unroll
    for (int mt = 0; mt < 4; mt++) {
        const int r0 = mBlock + mw + mt * 16 + gr;   // rows r0, r0+8
#pragma unroll
        for (int half = 0; half < 2; half++) {
            const int row = r0 + half * 8;
            float rm = 1.0f; int mi = 1;
            if (mode == 1 && rowmask) rm = rowmask[(long)b * M + row] ? 1.0f : 0.0f;
            if (mode == 2) mi = m1p[(long)b * M + row];
#pragma unroll
            for (int nt = 0; nt < 4; nt++) {
                const int c0 = nBlock + nw + nt * 8 + tg * 2;
                float v0 = acc[mt][nt][half * 2 + 0];
                float v1 = acc[mt][nt][half * 2 + 1];
                if (mode == 1) {
                    v0 += bias[c0];     v1 += bias[c0 + 1];
                    v0 = (v0 >= 0.0f) ? v0 : SLOPE * v0;
                    v1 = (v1 >= 0.0f) ? v1 : SLOPE * v1;
                    v0 *= rm; v1 *= rm;
                } else if (mode == 2) {
                    const int mj0 = m2p[(long)b * N + c0];
                    const int mj1 = m2p[(long)b * N + c0 + 1];
                    v0 += (mi && mj0) ? 0.0f : NEG_INF_F;
                    v1 += (mi && mj1) ? 0.0f : NEG_INF_F;
                }
                float2 o; o.x = v0; o.y = v1;
                *(float2*)&Cb[(long)row * ldC + c0] = o;
            }
        }
    }
}

// ---------------- batched transpose: dst[c][r] = src[r][c] ----------------
__global__ __launch_bounds__(256)
void transpose_kernel(const float* __restrict__ src, float* __restrict__ dst,
                      int rows, int cols, long sS, long sD)
{
    __shared__ float t[32][33];
    const float* s = src + (long)blockIdx.z * sS;
    float* d       = dst + (long)blockIdx.z * sD;
    const int x0 = blockIdx.x * 32;
    const int y0 = blockIdx.y * 32;
    const int tx = threadIdx.x, ty = threadIdx.y;
#pragma unroll
    for (int j = ty; j < 32; j += 8)
        t[j][tx] = s[(long)(y0 + j) * cols + x0 + tx];
    __syncthreads();
#pragma unroll
    for (int j = ty; j < 32; j += 8)
        d[(long)(x0 + j) * rows + y0 + tx] = t[tx][j];
}

// ---------------- Row softmax: o1[b,i,:] = softmax(S[b,i,:]) * mpos ----------------
__global__ __launch_bounds__(256)
void softmax_row_kernel(const float* __restrict__ S, float* __restrict__ O,
                        const int* __restrict__ m1, const int* __restrict__ m2)
{
    const int b = blockIdx.y, i = blockIdx.x;
    const float* row = S + ((long)b * Lc + i) * Lc;
    float* orow      = O + ((long)b * Lc + i) * Lc;
    const int tid = threadIdx.x;

    float v0 = row[tid], v1 = row[tid + 256];
    __shared__ float red[256];

    red[tid] = fmaxf(v0, v1);
    __syncthreads();
    for (int s = 128; s > 0; s >>= 1) {
        if (tid < s) red[tid] = fmaxf(red[tid], red[tid + s]);
        __syncthreads();
    }
    float mx = red[0];
    __syncthreads();

    float e0 = __expf(v0 - mx), e1 = __expf(v1 - mx);
    red[tid] = e0 + e1;
    __syncthreads();
    for (int s = 128; s > 0; s >>= 1) {
        if (tid < s) red[tid] += red[tid + s];
        __syncthreads();
    }
    float inv = 1.0f / red[0];

    int mi = m1[b * Lc + i];
    float f0 = (mi && m2[b * Lc + tid])       ? 1.0f : 0.0f;
    float f1 = (mi && m2[b * Lc + tid + 256]) ? 1.0f : 0.0f;
    orow[tid]       = e0 * inv * f0;
    orow[tid + 256] = e1 * inv * f1;
}

// -------- Column softmax, writes TRANSPOSED result: OT[b][j][i] --------
__global__ __launch_bounds__(1024)
void softmax_col_kernel(const float* __restrict__ S, float* __restrict__ OT,
                        const int* __restrict__ m1, const int* __restrict__ m2)
{
    const int b  = blockIdx.y;
    const int tx = threadIdx.x, ty = threadIdx.y;   // 32x32
    const int j  = blockIdx.x * 32 + tx;
    const float* Sb = S  + (long)b * Lc * Lc;
    float* OTb      = OT + (long)b * Lc * Lc;

    float vals[16];
    float lmax = -1e30f;
#pragma unroll
    for (int it = 0; it < 16; it++) {
        int i = ty + it * 32;
        vals[it] = Sb[(long)i * Lc + j];
        lmax = fmaxf(lmax, vals[it]);
    }
    __shared__ float red[32][33];
    red[ty][tx] = lmax;
    __syncthreads();
    for (int s = 16; s > 0; s >>= 1) {
        if (ty < s) red[ty][tx] = fmaxf(red[ty][tx], red[ty + s][tx]);
        __syncthreads();
    }
    float mx = red[0][tx];
    __syncthreads();

    float lsum = 0.0f;
#pragma unroll
    for (int it = 0; it < 16; it++) {
        vals[it] = __expf(vals[it] - mx);
        lsum += vals[it];
    }
    red[ty][tx] = lsum;
    __syncthreads();
    for (int s = 16; s > 0; s >>= 1) {
        if (ty < s) red[ty][tx] += red[ty + s][tx];
        __syncthreads();
    }
    float inv = 1.0f / red[0][tx];
    __syncthreads();

    const int mj = m2[b * Lc + j];
    const int j0 = blockIdx.x * 32;
#pragma unroll
    for (int it = 0; it < 16; it++) {
        int i = ty + it * 32;
        float f = (mj && m1[b * Lc + i]) ? 1.0f : 0.0f;
        float v = vals[it] * inv * f;
        red[ty][tx] = v;                 // value for (i = ty+it*32, j = j0+tx)
        __syncthreads();
        // thread (tx,ty) writes OT[j0+ty][it*32+tx] = value for (i=it*32+tx, j=j0+ty)
        OTb[(long)(j0 + ty) * Lc + it * 32 + tx] = red[tx][ty];
        __syncthreads();
    }
}

// ---------------- Launch ----------------
extern "C" void kernel_launch(void* const* d_in, const int* in_sizes, int n_in,
                              void* d_out, int out_size)
{
    const float* r1    = (const float*)d_in[0];
    const float* r2    = (const float*)d_in[1];
    const int*   mask1 = (const int*)  d_in[2];
    const int*   mask2 = (const int*)  d_in[3];
    const float* W1    = (const float*)d_in[4];
    const float* b1    = (const float*)d_in[5];
    const float* W2    = (const float*)d_in[6];
    const float* b2    = (const float*)d_in[7];
    const float* Wc1   = (const float*)d_in[8];   // [1024, 512]
    const float* bc1   = (const float*)d_in[9];
    const float* Wc2   = (const float*)d_in[10];
    const float* bc2   = (const float*)d_in[11];
    float* out = (float*)d_out;

    float *h, *r1m, *r2m, *r1mT, *r2mT, *S, *o1, *o2T, *c1, *c2;
    float *W1T, *W2T, *Wc1T, *Wc2T;
    cudaGetSymbolAddress((void**)&h,    g_h);
    cudaGetSymbolAddress((void**)&r1m,  g_r1m);
    cudaGetSymbolAddress((void**)&r2m,  g_r2m);
    cudaGetSymbolAddress((void**)&r1mT, g_r1mT);
    cudaGetSymbolAddress((void**)&r2mT, g_r2mT);
    cudaGetSymbolAddress((void**)&S,    g_S);
    cudaGetSymbolAddress((void**)&o1,   g_o1);
    cudaGetSymbolAddress((void**)&o2T,  g_o2T);
    cudaGetSymbolAddress((void**)&c1,   g_c1);
    cudaGetSymbolAddress((void**)&c2,   g_c2);
    cudaGetSymbolAddress((void**)&W1T,  g_W1T);
    cudaGetSymbolAddress((void**)&W2T,  g_W2T);
    cudaGetSymbolAddress((void**)&Wc1T, g_Wc1T);
    cudaGetSymbolAddress((void**)&Wc2T, g_Wc2T);

    const long LD = (long)Lc * Dc;   // 262144
    dim3 blk(256);
    dim3 gridMlp(Dc / BN, (Bc * Lc) / BM, 1);   // (4, 256, 1)
    dim3 gridBat(Dc / BN, Lc / BM, Bc);         // (4, 4, 64)
    dim3 tblk(32, 8);

    // ---- transpose weights (K-contiguous B operands) ----
    transpose_kernel<<<dim3(Dc/32, Dc/32, 1), tblk>>>(W1,  W1T,  Dc,   Dc, 0, 0);
    transpose_kernel<<<dim3(Dc/32, Dc/32, 1), tblk>>>(W2,  W2T,  Dc,   Dc, 0, 0);
    transpose_kernel<<<dim3(Dc/32, 2*Dc/32, 1), tblk>>>(Wc1, Wc1T, 2*Dc, Dc, 0, 0);
    transpose_kernel<<<dim3(Dc/32, Dc/32, 1), tblk>>>(Wc2, Wc2T, Dc,   Dc, 0, 0);

    // ---- MLP r1 ----
    gemm_tf32<<<gridMlp, blk>>>(r1, r1, W1T, h,
        Bc*Lc, Dc, Dc, Dc, Dc, Dc, Dc, Dc, 0, 0, 0, 0,
        b1, nullptr, nullptr, nullptr, 1);
    gemm_tf32<<<gridMlp, blk>>>(h, h, W2T, r1m,
        Bc*Lc, Dc, Dc, Dc, Dc, Dc, Dc, Dc, 0, 0, 0, 0,
        b2, mask1, nullptr, nullptr, 1);
    // ---- MLP r2 ----
    gemm_tf32<<<gridMlp, blk>>>(r2, r2, W1T, h,
        Bc*Lc, Dc, Dc, Dc, Dc, Dc, Dc, Dc, 0, 0, 0, 0,
        b1, nullptr, nullptr, nullptr, 1);
    gemm_tf32<<<gridMlp, blk>>>(h, h, W2T, r2m,
        Bc*Lc, Dc, Dc, Dc, Dc, Dc, Dc, Dc, 0, 0, 0, 0,
        b2, mask2, nullptr, nullptr, 1);

    // ---- Scores: S = r1m @ r2m^T + mask (both operands K(=d)-contiguous) ----
    gemm_tf32<<<dim3(Lc/BN, Lc/BM, Bc), blk>>>(r1m, r1m, r2m, S,
        Lc, Lc, Dc, Dc, Dc, Dc, Dc, Lc, LD, LD, LD, LD,
        nullptr, nullptr, mask1, mask2, 2);

    // ---- Softmaxes (col first writes o2^T; row writes o1) ----
    softmax_col_kernel<<<dim3(Lc/32, Bc), dim3(32, 32)>>>(S, o2T, mask1, mask2);
    softmax_row_kernel<<<dim3(Lc, Bc), 256>>>(S, o1, mask1, mask2);

    // ---- transpose activations for value GEMMs ----
    transpose_kernel<<<dim3(Dc/32, Lc/32, Bc), tblk>>>(r1m, r1mT, Lc, Dc, LD, LD);
    transpose_kernel<<<dim3(Dc/32, Lc/32, Bc), tblk>>>(r2m, r2mT, Lc, Dc, LD, LD);

    // ---- r1c = o1 @ r2m  (B = r2m^T stored as [D][L], K=j contiguous) ----
    gemm_tf32<<<gridBat, blk>>>(o1, o1, r2mT, c1,
        Lc, Dc, Lc, Lc, Lc, Lc, Lc, Dc, LD, LD, LD, LD,
        nullptr, nullptr, nullptr, nullptr, 0);
    // ---- r2c = o2^T @ r1m (A = o2T [j][i], B = r1m^T [D][L], K=i contiguous) ----
    gemm_tf32<<<gridBat, blk>>>(o2T, o2T, r1mT, c2,
        Lc, Dc, Lc, Lc, Lc, Lc, Lc, Dc, LD, LD, LD, LD,
        nullptr, nullptr, nullptr, nullptr, 0);

    // ---- Compare r1: [r1m | c1] @ Wc1T (K=1024), then @ Wc2T ----
    gemm_tf32<<<gridMlp, blk>>>(r1m, c1, Wc1T, h,
        Bc*Lc, Dc, 2*Dc, Dc, Dc, Dc, 2*Dc, Dc, 0, 0, 0, 0,
        bc1, nullptr, nullptr, nullptr, 1);
    gemm_tf32<<<gridMlp, blk>>>(h, h, Wc2T, out,
        Bc*Lc, Dc, Dc, Dc, Dc, Dc, Dc, Dc, 0, 0, 0, 0,
        bc2, mask1, nullptr, nullptr, 1);

    // ---- Compare r2 ----
    gemm_tf32<<<gridMlp, blk>>>(r2m, c2, Wc1T, h,
        Bc*Lc, Dc, 2*Dc, Dc, Dc, Dc, 2*Dc, Dc, 0, 0, 0, 0,
        bc1, nullptr, nullptr, nullptr, 1);
    gemm_tf32<<<gridMlp, blk>>>(h, h, Wc2T, out + (long)BLD,
        Bc*Lc, Dc, Dc, Dc, Dc, Dc, Dc, Dc, 0, 0, 0, 0,
        bc2, mask2, nullptr, nullptr, 1);
}